// round 4
// baseline (speedup 1.0000x reference)
#include <cuda_runtime.h>
#include <cstdint>
#include <cstddef>

// Problem constants
#define BATCH   4096
#define INDIM   10000
#define H1DIM   512
#define H2DIM   256
#define NPRIM   32
#define PDIM    8
#define NLAB    100
#define CDIM    16
#define PREDROW 51200   // 32*100*16
#define KSPLIT  5000    // INDIM / 2, divisible by 8

// ---------------- scratch (static device arrays; cudaMalloc forbidden) ------
__device__ float g_part[2][(size_t)BATCH * H1DIM];     // split-K partials
__device__ float g_h1[(size_t)BATCH * H1DIM];
__device__ float g_h2[(size_t)BATCH * H2DIM];
__device__ float g_p [(size_t)BATCH * H2DIM];          // p[b][n*8+o]
__device__ float g_WpT[H2DIM * (NPRIM * PDIM)];        // [i][n*8+o]
__device__ float g_preds[(size_t)BATCH * PREDROW];     // [b][n][j][o]  (839 MB)
__device__ float g_caps[(size_t)BATCH * NLAB * CDIM];  // [b][j][o]

// ---------------- K0: pack Wp [n][i][o] -> WpT [i][n*8+o] --------------------
__global__ void pack_wp(const float* __restrict__ Wp, float* __restrict__ WpT) {
    int idx = blockIdx.x * 256 + threadIdx.x;      // 65536 total
    int i = idx >> 8;
    int c = idx & 255;
    int n = c >> 3, o = c & 7;
    WpT[idx] = Wp[((size_t)(n << 8) + i) * 8 + o];
}

// ======== core 128x128x8 fp32 tile pipeline (double-buffered smem) ==========
// 256 threads, 8x8 micro-tile per thread. acc returned in-place.
struct TileCtx {
    int arow, acol, brow, bcol, ry, cx;
};

__device__ __forceinline__ void tile_init(TileCtx& t, int tid) {
    t.arow = tid >> 1;
    t.acol = (tid & 1) << 2;
    t.brow = tid >> 5;
    t.bcol = (tid & 31) << 2;
    t.ry = (tid >> 4) << 3;
    t.cx = (tid & 15) << 3;
}

__device__ __forceinline__ void tile_mainloop(
    const TileCtx& t, const float* Ap, const float* Bp, int N, int K,
    float (*As)[8][128], float (*Bs)[8][128], float acc[8][8])
{
    {
        float4 av = *(const float4*)(Ap);
        float4 bv = *(const float4*)(Bp);
        As[0][t.acol + 0][t.arow] = av.x;
        As[0][t.acol + 1][t.arow] = av.y;
        As[0][t.acol + 2][t.arow] = av.z;
        As[0][t.acol + 3][t.arow] = av.w;
        *(float4*)&Bs[0][t.brow][t.bcol] = bv;
    }
    __syncthreads();

    for (int k0 = 0; k0 < K; k0 += 8) {
        const int cur = (k0 >> 3) & 1;
        float4 av, bv;
        const bool more = (k0 + 8) < K;
        if (more) {
            av = *(const float4*)(Ap + k0 + 8);
            bv = *(const float4*)(Bp + (size_t)(k0 + 8) * N);
        }
#pragma unroll
        for (int kk = 0; kk < 8; ++kk) {
            float a[8], b[8];
            *(float4*)&a[0] = *(float4*)&As[cur][kk][t.ry];
            *(float4*)&a[4] = *(float4*)&As[cur][kk][t.ry + 4];
            *(float4*)&b[0] = *(float4*)&Bs[cur][kk][t.cx];
            *(float4*)&b[4] = *(float4*)&Bs[cur][kk][t.cx + 4];
#pragma unroll
            for (int i = 0; i < 8; ++i)
#pragma unroll
                for (int j = 0; j < 8; ++j) acc[i][j] += a[i] * b[j];
        }
        if (more) {
            const int nxt = cur ^ 1;
            As[nxt][t.acol + 0][t.arow] = av.x;
            As[nxt][t.acol + 1][t.arow] = av.y;
            As[nxt][t.acol + 2][t.arow] = av.z;
            As[nxt][t.acol + 3][t.arow] = av.w;
            *(float4*)&Bs[nxt][t.brow][t.bcol] = bv;
        }
        __syncthreads();
    }
}

// ---------------- SGEMM with bias + optional ReLU ----------------------------
template <bool RELU>
__global__ void __launch_bounds__(256) sgemm_k(
    const float* __restrict__ A, const float* __restrict__ Bm,
    const float* __restrict__ bias, float* __restrict__ C,
    int M, int N, int K)
{
    __shared__ float As[2][8][128];
    __shared__ float Bs[2][8][128];
    TileCtx t; tile_init(t, threadIdx.x);
    const int m0 = blockIdx.y * 128;
    const int n0 = blockIdx.x * 128;

    float acc[8][8];
#pragma unroll
    for (int i = 0; i < 8; ++i)
#pragma unroll
        for (int j = 0; j < 8; ++j) acc[i][j] = 0.f;

    tile_mainloop(t, A + (size_t)(m0 + t.arow) * K + t.acol,
                  Bm + (size_t)t.brow * N + n0 + t.bcol, N, K, As, Bs, acc);

    float4 bia = *(const float4*)&bias[n0 + t.cx];
    float4 bib = *(const float4*)&bias[n0 + t.cx + 4];
#pragma unroll
    for (int i = 0; i < 8; ++i) {
        float4 v0, v1;
        v0.x = acc[i][0] + bia.x; v0.y = acc[i][1] + bia.y;
        v0.z = acc[i][2] + bia.z; v0.w = acc[i][3] + bia.w;
        v1.x = acc[i][4] + bib.x; v1.y = acc[i][5] + bib.y;
        v1.z = acc[i][6] + bib.z; v1.w = acc[i][7] + bib.w;
        if (RELU) {
            v0.x = fmaxf(v0.x, 0.f); v0.y = fmaxf(v0.y, 0.f);
            v0.z = fmaxf(v0.z, 0.f); v0.w = fmaxf(v0.w, 0.f);
            v1.x = fmaxf(v1.x, 0.f); v1.y = fmaxf(v1.y, 0.f);
            v1.z = fmaxf(v1.z, 0.f); v1.w = fmaxf(v1.w, 0.f);
        }
        float* cp = C + (size_t)(m0 + t.ry + i) * N + n0 + t.cx;
        *(float4*)cp = v0;
        *(float4*)(cp + 4) = v1;
    }
}

// ---------------- split-K SGEMM (partial, no bias): gridDim.z picks K-half ---
__global__ void __launch_bounds__(256) sgemm_splitk(
    const float* __restrict__ A, const float* __restrict__ Bm,
    float* __restrict__ Cpart, int M, int N, int K)
{
    __shared__ float As[2][8][128];
    __shared__ float Bs[2][8][128];
    TileCtx t; tile_init(t, threadIdx.x);
    const int m0 = blockIdx.y * 128;
    const int n0 = blockIdx.x * 128;
    const int z  = blockIdx.z;
    const int kOff = z * KSPLIT;

    float acc[8][8];
#pragma unroll
    for (int i = 0; i < 8; ++i)
#pragma unroll
        for (int j = 0; j < 8; ++j) acc[i][j] = 0.f;

    tile_mainloop(t, A + (size_t)(m0 + t.arow) * K + kOff + t.acol,
                  Bm + (size_t)(kOff + t.brow) * N + n0 + t.bcol,
                  N, KSPLIT, As, Bs, acc);

    float* Cz = Cpart + (size_t)z * M * N;
#pragma unroll
    for (int i = 0; i < 8; ++i) {
        float* cp = Cz + (size_t)(m0 + t.ry + i) * N + n0 + t.cx;
        *(float4*)cp       = *(float4*)&acc[i][0];
        *(float4*)(cp + 4) = *(float4*)&acc[i][4];
    }
}

// ---------------- combine: h1 = relu(p0 + p1 + bias) -------------------------
__global__ void combine_relu(const float* __restrict__ part,
                             const float* __restrict__ bias,
                             float* __restrict__ out)
{
    int idx = blockIdx.x * 256 + threadIdx.x;    // over (B*H1)/4 float4s
    const float4* p0 = (const float4*)part;
    const float4* p1 = (const float4*)(part + (size_t)BATCH * H1DIM);
    float4 a = p0[idx], b = p1[idx];
    int col4 = (idx & (H1DIM / 4 - 1)) << 2;
    float4 bi = *(const float4*)&bias[col4];
    float4 r;
    r.x = fmaxf(a.x + b.x + bi.x, 0.f);
    r.y = fmaxf(a.y + b.y + bi.y, 0.f);
    r.z = fmaxf(a.z + b.z + bi.z, 0.f);
    r.w = fmaxf(a.w + b.w + bi.w, 0.f);
    ((float4*)out)[idx] = r;
}

// ---------------- LayerNorm over last dim (8) per (b, n) ---------------------
__global__ void ln_kernel(float* __restrict__ p,
                          const float* __restrict__ g,
                          const float* __restrict__ be)
{
    int idx = blockIdx.x * 256 + threadIdx.x;   // (b, n), 131072 total
    int n = idx & (NPRIM - 1);
    float* row = p + (size_t)idx * 8;
    float4 a = *(float4*)row;
    float4 b = *(float4*)(row + 4);
    float x[8] = {a.x, a.y, a.z, a.w, b.x, b.y, b.z, b.w};
    float mu = 0.f;
#pragma unroll
    for (int i = 0; i < 8; ++i) mu += x[i];
    mu *= 0.125f;
    float var = 0.f;
#pragma unroll
    for (int i = 0; i < 8; ++i) { float d = x[i] - mu; var += d * d; }
    var *= 0.125f;
    float inv = rsqrtf(var + 1e-5f);
    const float* gr = g + n * 8;
    const float* br = be + n * 8;
#pragma unroll
    for (int i = 0; i < 8; ++i) x[i] = (x[i] - mu) * inv * gr[i] + br[i];
    a.x = x[0]; a.y = x[1]; a.z = x[2]; a.w = x[3];
    b.x = x[4]; b.y = x[5]; b.z = x[6]; b.w = x[7];
    *(float4*)row = a;
    *(float4*)(row + 4) = b;
}

// ---------------- preds[b][n][j][o] = sum_i p[b][n][i] * Wr[n][j][o][i] ------
__global__ void __launch_bounds__(256) preds_kernel(
    const float* __restrict__ p, const float* __restrict__ Wr,
    float* __restrict__ preds)
{
    extern __shared__ float sm4[];
    float* ws = sm4;               // Wr[n]: 12800 floats
    float* ps = sm4 + 12800;       // 128 b x 8 = 1024 floats
    const int n  = blockIdx.y;
    const int b0 = blockIdx.x * 128;
    const int tid = threadIdx.x;
    const int lane = tid & 31, warp = tid >> 5;

    const float4* wg = (const float4*)(Wr + (size_t)n * 12800);
    float4* ws4 = (float4*)ws;
    for (int i = tid; i < 3200; i += 256) ws4[i] = wg[i];
    {
        int bb = tid >> 1, h = tid & 1;
        *(float4*)&ps[bb * 8 + h * 4] =
            *(const float4*)(p + (size_t)(b0 + bb) * 256 + n * 8 + h * 4);
    }
    __syncthreads();

    for (int chunk = warp; chunk < 13; chunk += 8) {
        int row0 = chunk * 128 + lane * 4;
        if (row0 >= 1600) continue;
        float w[4][8];
#pragma unroll
        for (int r = 0; r < 4; ++r) {
            float4 wa = *(float4*)&ws[(row0 + r) * 8];
            float4 wb = *(float4*)&ws[(row0 + r) * 8 + 4];
            w[r][0] = wa.x; w[r][1] = wa.y; w[r][2] = wa.z; w[r][3] = wa.w;
            w[r][4] = wb.x; w[r][5] = wb.y; w[r][6] = wb.z; w[r][7] = wb.w;
        }
#pragma unroll 2
        for (int bb = 0; bb < 128; ++bb) {
            float4 pa = *(float4*)&ps[bb * 8];
            float4 pb = *(float4*)&ps[bb * 8 + 4];
            float pv[8] = {pa.x, pa.y, pa.z, pa.w, pb.x, pb.y, pb.z, pb.w};
            float4 o;
            float* acc = (float*)&o;
#pragma unroll
            for (int r = 0; r < 4; ++r) {
                float s = 0.f;
#pragma unroll
                for (int i = 0; i < 8; ++i) s = fmaf(w[r][i], pv[i], s);
                acc[r] = s;
            }
            *(float4*)&preds[((size_t)(b0 + bb) * NPRIM + n) * 1600 + row0] = o;
        }
    }
}

// ---------------- dynamic routing, one CTA per batch element -----------------
__global__ void __launch_bounds__(256) routing_kernel(
    const float* __restrict__ preds, float* __restrict__ caps)
{
    extern __shared__ float sm[];
    float* sp = sm;                 // 51200
    float* Cw = sp + 51200;         // 3200
    float* S  = Cw + 3200;          // 1600
    float* SQ = S + 1600;           // 128
    const int tid = threadIdx.x;
    const int lane = tid & 31, warp = tid >> 5;
    const size_t b = blockIdx.x;

    const float4* g = (const float4*)(preds + b * PREDROW);
    float4* sp4 = (float4*)sp;
    for (int i = tid; i < 12800; i += 256) sp4[i] = g[i];
    __syncthreads();

    float bl[4][4];
#pragma unroll
    for (int q = 0; q < 4; ++q)
#pragma unroll
        for (int t = 0; t < 4; ++t) bl[q][t] = 0.f;

    for (int it = 0; it < 3; ++it) {
        if (it == 0) {
            for (int i = tid; i < 3200; i += 256) Cw[i] = 0.01f;
        } else {
#pragma unroll
            for (int q = 0; q < 4; ++q) {
                int n = warp * 4 + q;
                float m = -1e30f;
#pragma unroll
                for (int t = 0; t < 4; ++t) {
                    int j = lane + 32 * t;
                    if (j < NLAB) m = fmaxf(m, bl[q][t]);
                }
#pragma unroll
                for (int off = 16; off; off >>= 1)
                    m = fmaxf(m, __shfl_xor_sync(0xffffffffu, m, off));
                float e[4]; float s = 0.f;
#pragma unroll
                for (int t = 0; t < 4; ++t) {
                    int j = lane + 32 * t;
                    e[t] = (j < NLAB) ? __expf(bl[q][t] - m) : 0.f;
                    s += e[t];
                }
#pragma unroll
                for (int off = 16; off; off >>= 1)
                    s += __shfl_xor_sync(0xffffffffu, s, off);
                float inv = 1.f / s;
#pragma unroll
                for (int t = 0; t < 4; ++t) {
                    int j = lane + 32 * t;
                    if (j < NLAB) Cw[n * NLAB + j] = e[t] * inv;
                }
            }
        }
        __syncthreads();

        for (int idx = tid; idx < 400; idx += 256) {
            int j = idx >> 2, o4 = (idx & 3) << 2;
            float4 acc = {0.f, 0.f, 0.f, 0.f};
#pragma unroll 4
            for (int n = 0; n < NPRIM; ++n) {
                float c = Cw[n * NLAB + j];
                float4 pv = *(float4*)&sp[((n * NLAB + j) << 4) + o4];
                acc.x = fmaf(c, pv.x, acc.x);
                acc.y = fmaf(c, pv.y, acc.y);
                acc.z = fmaf(c, pv.z, acc.z);
                acc.w = fmaf(c, pv.w, acc.w);
            }
            *(float4*)&S[(j << 4) + o4] = acc;
        }
        __syncthreads();

        for (int j = tid; j < NLAB; j += 256) {
            float sq = 0.f;
#pragma unroll
            for (int o = 0; o < CDIM; ++o) { float v = S[(j << 4) + o]; sq = fmaf(v, v, sq); }
            SQ[j] = sq;
        }
        __syncthreads();
        for (int idx = tid; idx < 400; idx += 256) {
            int j = idx >> 2, o4 = (idx & 3) << 2;
            float sq = SQ[j];
            float scale = sq / ((1.f + sq) * sqrtf(sq + 1e-8f));
            float4 v = *(float4*)&S[(j << 4) + o4];
            v.x *= scale; v.y *= scale; v.z *= scale; v.w *= scale;
            *(float4*)&S[(j << 4) + o4] = v;
        }
        __syncthreads();

        if (it < 2) {
#pragma unroll
            for (int q = 0; q < 4; ++q) {
                int n = warp * 4 + q;
#pragma unroll
                for (int t = 0; t < 4; ++t) {
                    int j = lane + 32 * t;
                    if (j < NLAB) {
                        const float* pr = &sp[(n * NLAB + j) << 4];
                        const float* vv = &S[j << 4];
                        float a = 0.f;
#pragma unroll
                        for (int o = 0; o < CDIM; o += 4) {
                            float4 pv = *(float4*)&pr[o];
                            float4 sv = *(float4*)&vv[o];
                            a = fmaf(pv.x, sv.x, a);
                            a = fmaf(pv.y, sv.y, a);
                            a = fmaf(pv.z, sv.z, a);
                            a = fmaf(pv.w, sv.w, a);
                        }
                        bl[q][t] += a;
                    }
                }
            }
            __syncthreads();
        } else {
            for (int idx = tid; idx < 400; idx += 256) {
                int j = idx >> 2, o4 = (idx & 3) << 2;
                *(float4*)&caps[b * 1600 + (j << 4) + o4] = *(float4*)&S[(j << 4) + o4];
            }
        }
    }
}

// ---------------- final: logits = caps @ Wc + bc -----------------------------
__global__ void __launch_bounds__(256) final_gemm(
    const float* __restrict__ caps, const float* __restrict__ Wc,
    const float* __restrict__ bc, float* __restrict__ out)
{
    extern __shared__ float sc[];   // 16 * 1600 floats
    const int b0 = blockIdx.x * 16;
    const int tid = threadIdx.x;
    const float4* g = (const float4*)(caps + (size_t)b0 * 1600);
    float4* s4 = (float4*)sc;
    for (int i = tid; i < 6400; i += 256) s4[i] = g[i];
    __syncthreads();

    for (int t = tid; t < 400; t += 256) {
        int bs = t / 25;
        int c4 = (t % 25) * 4;
        const float* crow = &sc[bs * 1600];
        float4 acc = *(const float4*)&bc[c4];
#pragma unroll 4
        for (int k = 0; k < 1600; ++k) {
            float cv = crow[k];
            float4 w = *(const float4*)&Wc[k * NLAB + c4];
            acc.x = fmaf(cv, w.x, acc.x);
            acc.y = fmaf(cv, w.y, acc.y);
            acc.z = fmaf(cv, w.z, acc.z);
            acc.w = fmaf(cv, w.w, acc.w);
        }
        *(float4*)&out[(size_t)(b0 + bs) * NLAB + c4] = acc;
    }
}

// ---------------- launch -----------------------------------------------------
extern "C" void kernel_launch(void* const* d_in, const int* in_sizes, int n_in,
                              void* d_out, int out_size)
{
    const float* F  = (const float*)d_in[0];
    const float* W1 = (const float*)d_in[1];
    const float* b1 = (const float*)d_in[2];
    const float* W2 = (const float*)d_in[3];
    const float* b2 = (const float*)d_in[4];
    const float* Wp = (const float*)d_in[5];
    const float* bp = (const float*)d_in[6];
    const float* lg = (const float*)d_in[7];
    const float* lb = (const float*)d_in[8];
    const float* Wr = (const float*)d_in[9];
    const float* Wc = (const float*)d_in[10];
    const float* bc = (const float*)d_in[11];
    float* out = (float*)d_out;
    (void)in_sizes; (void)n_in; (void)out_size;

    float *part, *h1, *h2, *p, *wpt, *pr, *caps;
    cudaGetSymbolAddress((void**)&part, g_part);
    cudaGetSymbolAddress((void**)&h1,   g_h1);
    cudaGetSymbolAddress((void**)&h2,   g_h2);
    cudaGetSymbolAddress((void**)&p,    g_p);
    cudaGetSymbolAddress((void**)&wpt,  g_WpT);
    cudaGetSymbolAddress((void**)&pr,   g_preds);
    cudaGetSymbolAddress((void**)&caps, g_caps);

    cudaFuncSetAttribute((const void*)preds_kernel,
                         cudaFuncAttributeMaxDynamicSharedMemorySize, 55296);
    cudaFuncSetAttribute((const void*)routing_kernel,
                         cudaFuncAttributeMaxDynamicSharedMemorySize, 224512);
    cudaFuncSetAttribute((const void*)final_gemm,
                         cudaFuncAttributeMaxDynamicSharedMemorySize, 102400);

    pack_wp<<<256, 256>>>(Wp, wpt);
    // GEMM1 split-K: 256 CTAs in one launch
    sgemm_splitk<<<dim3(4, 32, 2), 256>>>(F, W1, part, BATCH, H1DIM, INDIM);
    combine_relu<<<(BATCH * H1DIM) / 4 / 256, 256>>>(part, b1, h1);
    sgemm_k<true ><<<dim3(2, 32), 256>>>(h1, W2,  b2, h2, BATCH, H2DIM, H1DIM);
    sgemm_k<false><<<dim3(2, 32), 256>>>(h2, wpt, bp, p,  BATCH, H2DIM, H2DIM);
    ln_kernel<<<(BATCH * NPRIM) / 256, 256>>>(p, lg, lb);
    preds_kernel<<<dim3(BATCH / 128, NPRIM), 256, 55296>>>(p, Wr, pr);
    routing_kernel<<<BATCH, 256, 224512>>>(pr, caps);
    final_gemm<<<BATCH / 16, 256, 102400>>>(caps, Wc, bc, out);
}

// round 5
// speedup vs baseline: 1.2135x; 1.2135x over previous
#include <cuda_runtime.h>
#include <cuda_bf16.h>
#include <cstdint>
#include <cstddef>

// Problem constants
#define BATCH   4096
#define INDIM   10000
#define KPAD    10016      // INDIM padded to multiple of 32
#define H1DIM   512
#define H2DIM   256
#define NPRIM   32
#define PDIM    8
#define NLAB    100
#define CDIM    16
#define PREDROW 51200      // 32*100*16

// ---------------- scratch (static device arrays; cudaMalloc forbidden) ------
__device__ __nv_bfloat16 g_Fhi[(size_t)BATCH * KPAD];
__device__ __nv_bfloat16 g_Flo[(size_t)BATCH * KPAD];
__device__ __nv_bfloat16 g_W1Thi[(size_t)H1DIM * KPAD];   // [n][k] transposed
__device__ __nv_bfloat16 g_W1Tlo[(size_t)H1DIM * KPAD];
__device__ float g_h1[(size_t)BATCH * H1DIM];
__device__ float g_h2[(size_t)BATCH * H2DIM];
__device__ float g_p [(size_t)BATCH * H2DIM];
__device__ float g_WpT[H2DIM * (NPRIM * PDIM)];
__device__ float g_preds[(size_t)BATCH * PREDROW];        // 839 MB
__device__ float g_caps[(size_t)BATCH * NLAB * CDIM];

// ---------------- conversions ------------------------------------------------
__global__ void convert_F(const float* __restrict__ F,
                          __nv_bfloat16* __restrict__ hi,
                          __nv_bfloat16* __restrict__ lo)
{
    int k = blockIdx.x * 256 + threadIdx.x;
    int b = blockIdx.y;
    if (k >= KPAD) return;
    float x = (k < INDIM) ? F[(size_t)b * INDIM + k] : 0.f;
    __nv_bfloat16 h = __float2bfloat16_rn(x);
    float r = x - __bfloat162float(h);
    hi[(size_t)b * KPAD + k] = h;
    lo[(size_t)b * KPAD + k] = __float2bfloat16_rn(r);
}

// transpose W1 [k][n] -> W1T [n][k] with hi/lo split; tiled via smem
__global__ void convert_W1T(const float* __restrict__ W1,
                            __nv_bfloat16* __restrict__ hi,
                            __nv_bfloat16* __restrict__ lo)
{
    __shared__ float tile[32][33];
    int k0 = blockIdx.x * 32;
    int n0 = blockIdx.y * 32;
    int tx = threadIdx.x, ty = threadIdx.y;   // 32 x 8
#pragma unroll
    for (int i = 0; i < 4; ++i) {
        int k = k0 + ty + i * 8;
        tile[ty + i * 8][tx] = (k < INDIM) ? W1[(size_t)k * H1DIM + n0 + tx] : 0.f;
    }
    __syncthreads();
#pragma unroll
    for (int i = 0; i < 4; ++i) {
        int n = n0 + ty + i * 8;
        int k = k0 + tx;
        float x = tile[tx][ty + i * 8];
        __nv_bfloat16 h = __float2bfloat16_rn(x);
        float r = x - __bfloat162float(h);
        hi[(size_t)n * KPAD + k] = h;
        lo[(size_t)n * KPAD + k] = __float2bfloat16_rn(r);
    }
}

// ---------------- cp.async helpers -------------------------------------------
__device__ __forceinline__ void cp16(uint32_t dst, const void* src) {
    asm volatile("cp.async.cg.shared.global [%0], [%1], 16;\n" :: "r"(dst), "l"(src));
}
__device__ __forceinline__ void cp_commit() {
    asm volatile("cp.async.commit_group;\n");
}
template <int N>
__device__ __forceinline__ void cp_wait() {
    asm volatile("cp.async.wait_group %0;\n" :: "n"(N));
}

__device__ __forceinline__ void mma_bf16(float* d,
    uint32_t a0, uint32_t a1, uint32_t a2, uint32_t a3,
    uint32_t b0, uint32_t b1)
{
    asm volatile(
        "mma.sync.aligned.m16n8k16.row.col.f32.bf16.bf16.f32 "
        "{%0,%1,%2,%3}, {%4,%5,%6,%7}, {%8,%9}, {%0,%1,%2,%3};\n"
        : "+f"(d[0]), "+f"(d[1]), "+f"(d[2]), "+f"(d[3])
        : "r"(a0), "r"(a1), "r"(a2), "r"(a3), "r"(b0), "r"(b1));
}

// ---------------- GEMM1: h1 = relu(F @ W1 + b1), bf16 split 3-term MMA -------
// BM=128, BN=128, BK=32. 256 threads = 8 warps (2x4), warp tile 64x32.
// smem per stage: Ahi/Alo/Bhi/Blo each [128][40] bf16 (40 = 32 + 8 pad) = 10240B
#define STG_BYTES 40960            // 4 * 10240
#define ROWU32 20                  // 40 bf16 = 20 u32 per row

__global__ void __launch_bounds__(256) gemm1_bf16(
    const __nv_bfloat16* __restrict__ Ahi, const __nv_bfloat16* __restrict__ Alo,
    const __nv_bfloat16* __restrict__ Bhi, const __nv_bfloat16* __restrict__ Blo,
    const float* __restrict__ bias, float* __restrict__ C)
{
    extern __shared__ __align__(16) char dsm[];
    const int tid  = threadIdx.x;
    const int lane = tid & 31, warp = tid >> 5;
    const int g = lane >> 2, tg = lane & 3;
    const int wm = warp >> 2, wn = warp & 3;          // 2 x 4 warp grid
    const int m0 = blockIdx.y * 128;
    const int n0 = blockIdx.x * 128;

    uint32_t smem_u32;
    { void* p = dsm; smem_u32 = (uint32_t)__cvta_generic_to_shared(p); }

    // loader mapping: chunk c in [0,512): row = c>>2, kc = c&3 (16B each)
    const int c0 = tid, c1 = tid + 256;
    const int r0 = c0 >> 2, kc0 = c0 & 3;
    const int r1 = c1 >> 2, kc1 = c1 & 3;

    float acc[4][4][4];
#pragma unroll
    for (int a = 0; a < 4; ++a)
#pragma unroll
        for (int b = 0; b < 4; ++b)
#pragma unroll
            for (int d = 0; d < 4; ++d) acc[a][b][d] = 0.f;

    const int NSTEP = KPAD / 32;    // 313

    // stage loader
    auto load_stage = [&](int stage, int k0) {
        uint32_t base = smem_u32 + stage * STG_BYTES;
        // A hi/lo
        cp16(base + r0 * 80 + kc0 * 16,          Ahi + (size_t)(m0 + r0) * KPAD + k0 + kc0 * 8);
        cp16(base + r1 * 80 + kc1 * 16,          Ahi + (size_t)(m0 + r1) * KPAD + k0 + kc1 * 8);
        cp16(base + 10240 + r0 * 80 + kc0 * 16,  Alo + (size_t)(m0 + r0) * KPAD + k0 + kc0 * 8);
        cp16(base + 10240 + r1 * 80 + kc1 * 16,  Alo + (size_t)(m0 + r1) * KPAD + k0 + kc1 * 8);
        // B hi/lo (row index = n-local)
        cp16(base + 20480 + r0 * 80 + kc0 * 16,  Bhi + (size_t)(n0 + r0) * KPAD + k0 + kc0 * 8);
        cp16(base + 20480 + r1 * 80 + kc1 * 16,  Bhi + (size_t)(n0 + r1) * KPAD + k0 + kc1 * 8);
        cp16(base + 30720 + r0 * 80 + kc0 * 16,  Blo + (size_t)(n0 + r0) * KPAD + k0 + kc0 * 8);
        cp16(base + 30720 + r1 * 80 + kc1 * 16,  Blo + (size_t)(n0 + r1) * KPAD + k0 + kc1 * 8);
    };

    load_stage(0, 0);
    cp_commit();

    for (int it = 0; it < NSTEP; ++it) {
        const int stage = it & 1;
        if (it + 1 < NSTEP) {
            load_stage(stage ^ 1, (it + 1) * 32);
            cp_commit();
            cp_wait<1>();
        } else {
            cp_wait<0>();
        }
        __syncthreads();

        const uint32_t* Ah = (const uint32_t*)(dsm + stage * STG_BYTES);
        const uint32_t* Al = Ah + 10240 / 4;
        const uint32_t* Bh = Ah + 20480 / 4;
        const uint32_t* Bl = Ah + 30720 / 4;

#pragma unroll
        for (int ks = 0; ks < 2; ++ks) {
            uint32_t ah[4][4], al[4][4], bh[4][2], bl[4][2];
#pragma unroll
            for (int mi = 0; mi < 4; ++mi) {
                int row = wm * 64 + mi * 16 + g;
                int o = ks * 8 + tg;
                ah[mi][0] = Ah[row * ROWU32 + o];
                ah[mi][1] = Ah[(row + 8) * ROWU32 + o];
                ah[mi][2] = Ah[row * ROWU32 + o + 4];
                ah[mi][3] = Ah[(row + 8) * ROWU32 + o + 4];
                al[mi][0] = Al[row * ROWU32 + o];
                al[mi][1] = Al[(row + 8) * ROWU32 + o];
                al[mi][2] = Al[row * ROWU32 + o + 4];
                al[mi][3] = Al[(row + 8) * ROWU32 + o + 4];
            }
#pragma unroll
            for (int ni = 0; ni < 4; ++ni) {
                int row = wn * 32 + ni * 8 + g;
                int o = ks * 8 + tg;
                bh[ni][0] = Bh[row * ROWU32 + o];
                bh[ni][1] = Bh[row * ROWU32 + o + 4];
                bl[ni][0] = Bl[row * ROWU32 + o];
                bl[ni][1] = Bl[row * ROWU32 + o + 4];
            }
#pragma unroll
            for (int mi = 0; mi < 4; ++mi)
#pragma unroll
                for (int ni = 0; ni < 4; ++ni) {
                    mma_bf16(acc[mi][ni], ah[mi][0], ah[mi][1], ah[mi][2], ah[mi][3],
                             bh[ni][0], bh[ni][1]);
                    mma_bf16(acc[mi][ni], ah[mi][0], ah[mi][1], ah[mi][2], ah[mi][3],
                             bl[ni][0], bl[ni][1]);
                    mma_bf16(acc[mi][ni], al[mi][0], al[mi][1], al[mi][2], al[mi][3],
                             bh[ni][0], bh[ni][1]);
                }
        }
        __syncthreads();
    }

    // epilogue: bias + relu, fp32 out
#pragma unroll
    for (int mi = 0; mi < 4; ++mi) {
        int row = m0 + wm * 64 + mi * 16 + g;
#pragma unroll
        for (int ni = 0; ni < 4; ++ni) {
            int col = n0 + wn * 32 + ni * 8 + tg * 2;
            float2 bv = *(const float2*)&bias[col];
            float2 v0, v1;
            v0.x = fmaxf(acc[mi][ni][0] + bv.x, 0.f);
            v0.y = fmaxf(acc[mi][ni][1] + bv.y, 0.f);
            v1.x = fmaxf(acc[mi][ni][2] + bv.x, 0.f);
            v1.y = fmaxf(acc[mi][ni][3] + bv.y, 0.f);
            *(float2*)&C[(size_t)row * H1DIM + col] = v0;
            *(float2*)&C[(size_t)(row + 8) * H1DIM + col] = v1;
        }
    }
}

// ---------------- K0: pack Wp [n][i][o] -> WpT [i][n*8+o] --------------------
__global__ void pack_wp(const float* __restrict__ Wp, float* __restrict__ WpT) {
    int idx = blockIdx.x * 256 + threadIdx.x;
    int i = idx >> 8;
    int c = idx & 255;
    int n = c >> 3, o = c & 7;
    WpT[idx] = Wp[((size_t)(n << 8) + i) * 8 + o];
}

// ---------------- fp32 SIMT SGEMM (GEMM2/GEMM3) ------------------------------
struct TileCtx { int arow, acol, brow, bcol, ry, cx; };
__device__ __forceinline__ void tile_init(TileCtx& t, int tid) {
    t.arow = tid >> 1;  t.acol = (tid & 1) << 2;
    t.brow = tid >> 5;  t.bcol = (tid & 31) << 2;
    t.ry = (tid >> 4) << 3;  t.cx = (tid & 15) << 3;
}
__device__ __forceinline__ void tile_mainloop(
    const TileCtx& t, const float* Ap, const float* Bp, int N, int K,
    float (*As)[8][128], float (*Bs)[8][128], float acc[8][8])
{
    {
        float4 av = *(const float4*)(Ap);
        float4 bv = *(const float4*)(Bp);
        As[0][t.acol + 0][t.arow] = av.x;
        As[0][t.acol + 1][t.arow] = av.y;
        As[0][t.acol + 2][t.arow] = av.z;
        As[0][t.acol + 3][t.arow] = av.w;
        *(float4*)&Bs[0][t.brow][t.bcol] = bv;
    }
    __syncthreads();
    for (int k0 = 0; k0 < K; k0 += 8) {
        const int cur = (k0 >> 3) & 1;
        float4 av, bv;
        const bool more = (k0 + 8) < K;
        if (more) {
            av = *(const float4*)(Ap + k0 + 8);
            bv = *(const float4*)(Bp + (size_t)(k0 + 8) * N);
        }
#pragma unroll
        for (int kk = 0; kk < 8; ++kk) {
            float a[8], b[8];
            *(float4*)&a[0] = *(float4*)&As[cur][kk][t.ry];
            *(float4*)&a[4] = *(float4*)&As[cur][kk][t.ry + 4];
            *(float4*)&b[0] = *(float4*)&Bs[cur][kk][t.cx];
            *(float4*)&b[4] = *(float4*)&Bs[cur][kk][t.cx + 4];
#pragma unroll
            for (int i = 0; i < 8; ++i)
#pragma unroll
                for (int j = 0; j < 8; ++j) acc[i][j] += a[i] * b[j];
        }
        if (more) {
            const int nxt = cur ^ 1;
            As[nxt][t.acol + 0][t.arow] = av.x;
            As[nxt][t.acol + 1][t.arow] = av.y;
            As[nxt][t.acol + 2][t.arow] = av.z;
            As[nxt][t.acol + 3][t.arow] = av.w;
            *(float4*)&Bs[nxt][t.brow][t.bcol] = bv;
        }
        __syncthreads();
    }
}

template <bool RELU>
__global__ void __launch_bounds__(256) sgemm_k(
    const float* __restrict__ A, const float* __restrict__ Bm,
    const float* __restrict__ bias, float* __restrict__ C,
    int M, int N, int K)
{
    __shared__ float As[2][8][128];
    __shared__ float Bs[2][8][128];
    TileCtx t; tile_init(t, threadIdx.x);
    const int m0 = blockIdx.y * 128;
    const int n0 = blockIdx.x * 128;

    float acc[8][8];
#pragma unroll
    for (int i = 0; i < 8; ++i)
#pragma unroll
        for (int j = 0; j < 8; ++j) acc[i][j] = 0.f;

    tile_mainloop(t, A + (size_t)(m0 + t.arow) * K + t.acol,
                  Bm + (size_t)t.brow * N + n0 + t.bcol, N, K, As, Bs, acc);

    float4 bia = *(const float4*)&bias[n0 + t.cx];
    float4 bib = *(const float4*)&bias[n0 + t.cx + 4];
#pragma unroll
    for (int i = 0; i < 8; ++i) {
        float4 v0, v1;
        v0.x = acc[i][0] + bia.x; v0.y = acc[i][1] + bia.y;
        v0.z = acc[i][2] + bia.z; v0.w = acc[i][3] + bia.w;
        v1.x = acc[i][4] + bib.x; v1.y = acc[i][5] + bib.y;
        v1.z = acc[i][6] + bib.z; v1.w = acc[i][7] + bib.w;
        if (RELU) {
            v0.x = fmaxf(v0.x, 0.f); v0.y = fmaxf(v0.y, 0.f);
            v0.z = fmaxf(v0.z, 0.f); v0.w = fmaxf(v0.w, 0.f);
            v1.x = fmaxf(v1.x, 0.f); v1.y = fmaxf(v1.y, 0.f);
            v1.w = fmaxf(v1.w, 0.f); v1.z = fmaxf(v1.z, 0.f);
        }
        float* cp = C + (size_t)(m0 + t.ry + i) * N + n0 + t.cx;
        *(float4*)cp = v0;
        *(float4*)(cp + 4) = v1;
    }
}

// ---------------- LayerNorm over last dim (8) per (b, n) ---------------------
__global__ void ln_kernel(float* __restrict__ p,
                          const float* __restrict__ g,
                          const float* __restrict__ be)
{
    int idx = blockIdx.x * 256 + threadIdx.x;
    int n = idx & (NPRIM - 1);
    float* row = p + (size_t)idx * 8;
    float4 a = *(float4*)row;
    float4 b = *(float4*)(row + 4);
    float x[8] = {a.x, a.y, a.z, a.w, b.x, b.y, b.z, b.w};
    float mu = 0.f;
#pragma unroll
    for (int i = 0; i < 8; ++i) mu += x[i];
    mu *= 0.125f;
    float var = 0.f;
#pragma unroll
    for (int i = 0; i < 8; ++i) { float d = x[i] - mu; var += d * d; }
    var *= 0.125f;
    float inv = rsqrtf(var + 1e-5f);
    const float* gr = g + n * 8;
    const float* br = be + n * 8;
#pragma unroll
    for (int i = 0; i < 8; ++i) x[i] = (x[i] - mu) * inv * gr[i] + br[i];
    a.x = x[0]; a.y = x[1]; a.z = x[2]; a.w = x[3];
    b.x = x[4]; b.y = x[5]; b.z = x[6]; b.w = x[7];
    *(float4*)row = a;
    *(float4*)(row + 4) = b;
}

// ---------------- preds[b][n][j][o] = sum_i p[b][n][i] * Wr[n][j][o][i] ------
__global__ void __launch_bounds__(256) preds_kernel(
    const float* __restrict__ p, const float* __restrict__ Wr,
    float* __restrict__ preds)
{
    extern __shared__ float sm4[];
    float* ws = sm4;
    float* ps = sm4 + 12800;
    const int n  = blockIdx.y;
    const int b0 = blockIdx.x * 128;
    const int tid = threadIdx.x;
    const int lane = tid & 31, warp = tid >> 5;

    const float4* wg = (const float4*)(Wr + (size_t)n * 12800);
    float4* ws4 = (float4*)ws;
    for (int i = tid; i < 3200; i += 256) ws4[i] = wg[i];
    {
        int bb = tid >> 1, h = tid & 1;
        *(float4*)&ps[bb * 8 + h * 4] =
            *(const float4*)(p + (size_t)(b0 + bb) * 256 + n * 8 + h * 4);
    }
    __syncthreads();

    for (int chunk = warp; chunk < 13; chunk += 8) {
        int row0 = chunk * 128 + lane * 4;
        if (row0 >= 1600) continue;
        float w[4][8];
#pragma unroll
        for (int r = 0; r < 4; ++r) {
            float4 wa = *(float4*)&ws[(row0 + r) * 8];
            float4 wb = *(float4*)&ws[(row0 + r) * 8 + 4];
            w[r][0] = wa.x; w[r][1] = wa.y; w[r][2] = wa.z; w[r][3] = wa.w;
            w[r][4] = wb.x; w[r][5] = wb.y; w[r][6] = wb.z; w[r][7] = wb.w;
        }
#pragma unroll 2
        for (int bb = 0; bb < 128; ++bb) {
            float4 pa = *(float4*)&ps[bb * 8];
            float4 pb = *(float4*)&ps[bb * 8 + 4];
            float pv[8] = {pa.x, pa.y, pa.z, pa.w, pb.x, pb.y, pb.z, pb.w};
            float4 o;
            float* acc = (float*)&o;
#pragma unroll
            for (int r = 0; r < 4; ++r) {
                float s = 0.f;
#pragma unroll
                for (int i = 0; i < 8; ++i) s = fmaf(w[r][i], pv[i], s);
                acc[r] = s;
            }
            *(float4*)&preds[((size_t)(b0 + bb) * NPRIM + n) * 1600 + row0] = o;
        }
    }
}

// ---------------- dynamic routing, one CTA per batch element -----------------
__global__ void __launch_bounds__(256) routing_kernel(
    const float* __restrict__ preds, float* __restrict__ caps)
{
    extern __shared__ float sm[];
    float* sp = sm;                 // 51200
    float* Cw = sp + 51200;         // 3200
    float* S  = Cw + 3200;          // 1600
    float* SQ = S + 1600;           // 128
    const int tid = threadIdx.x;
    const int lane = tid & 31, warp = tid >> 5;
    const size_t b = blockIdx.x;

    const float4* g = (const float4*)(preds + b * PREDROW);
    float4* sp4 = (float4*)sp;
    for (int i = tid; i < 12800; i += 256) sp4[i] = g[i];
    __syncthreads();

    float bl[4][4];
#pragma unroll
    for (int q = 0; q < 4; ++q)
#pragma unroll
        for (int t = 0; t < 4; ++t) bl[q][t] = 0.f;

    for (int it = 0; it < 3; ++it) {
        if (it == 0) {
            for (int i = tid; i < 3200; i += 256) Cw[i] = 0.01f;
        } else {
#pragma unroll
            for (int q = 0; q < 4; ++q) {
                int n = warp * 4 + q;
                float m = -1e30f;
#pragma unroll
                for (int t = 0; t < 4; ++t) {
                    int j = lane + 32 * t;
                    if (j < NLAB) m = fmaxf(m, bl[q][t]);
                }
#pragma unroll
                for (int off = 16; off; off >>= 1)
                    m = fmaxf(m, __shfl_xor_sync(0xffffffffu, m, off));
                float e[4]; float s = 0.f;
#pragma unroll
                for (int t = 0; t < 4; ++t) {
                    int j = lane + 32 * t;
                    e[t] = (j < NLAB) ? __expf(bl[q][t] - m) : 0.f;
                    s += e[t];
                }
#pragma unroll
                for (int off = 16; off; off >>= 1)
                    s += __shfl_xor_sync(0xffffffffu, s, off);
                float inv = 1.f / s;
#pragma unroll
                for (int t = 0; t < 4; ++t) {
                    int j = lane + 32 * t;
                    if (j < NLAB) Cw[n * NLAB + j] = e[t] * inv;
                }
            }
        }
        __syncthreads();

        for (int idx = tid; idx < 400; idx += 256) {
            int j = idx >> 2, o4 = (idx & 3) << 2;
            float4 acc = {0.f, 0.f, 0.f, 0.f};
#pragma unroll 4
            for (int n = 0; n < NPRIM; ++n) {
                float c = Cw[n * NLAB + j];
                float4 pv = *(float4*)&sp[((n * NLAB + j) << 4) + o4];
                acc.x = fmaf(c, pv.x, acc.x);
                acc.y = fmaf(c, pv.y, acc.y);
                acc.z = fmaf(c, pv.z, acc.z);
                acc.w = fmaf(c, pv.w, acc.w);
            }
            *(float4*)&S[(j << 4) + o4] = acc;
        }
        __syncthreads();

        for (int j = tid; j < NLAB; j += 256) {
            float sq = 0.f;
#pragma unroll
            for (int o = 0; o < CDIM; ++o) { float v = S[(j << 4) + o]; sq = fmaf(v, v, sq); }
            SQ[j] = sq;
        }
        __syncthreads();
        for (int idx = tid; idx < 400; idx += 256) {
            int j = idx >> 2, o4 = (idx & 3) << 2;
            float sq = SQ[j];
            float scale = sq / ((1.f + sq) * sqrtf(sq + 1e-8f));
            float4 v = *(float4*)&S[(j << 4) + o4];
            v.x *= scale; v.y *= scale; v.z *= scale; v.w *= scale;
            *(float4*)&S[(j << 4) + o4] = v;
        }
        __syncthreads();

        if (it < 2) {
#pragma unroll
            for (int q = 0; q < 4; ++q) {
                int n = warp * 4 + q;
#pragma unroll
                for (int t = 0; t < 4; ++t) {
                    int j = lane + 32 * t;
                    if (j < NLAB) {
                        const float* pr = &sp[(n * NLAB + j) << 4];
                        const float* vv = &S[j << 4];
                        float a = 0.f;
#pragma unroll
                        for (int o = 0; o < CDIM; o += 4) {
                            float4 pv = *(float4*)&pr[o];
                            float4 sv = *(float4*)&vv[o];
                            a = fmaf(pv.x, sv.x, a);
                            a = fmaf(pv.y, sv.y, a);
                            a = fmaf(pv.z, sv.z, a);
                            a = fmaf(pv.w, sv.w, a);
                        }
                        bl[q][t] += a;
                    }
                }
            }
            __syncthreads();
        } else {
            for (int idx = tid; idx < 400; idx += 256) {
                int j = idx >> 2, o4 = (idx & 3) << 2;
                *(float4*)&caps[b * 1600 + (j << 4) + o4] = *(float4*)&S[(j << 4) + o4];
            }
        }
    }
}

// ---------------- final: logits = caps @ Wc + bc -----------------------------
__global__ void __launch_bounds__(256) final_gemm(
    const float* __restrict__ caps, const float* __restrict__ Wc,
    const float* __restrict__ bc, float* __restrict__ out)
{
    extern __shared__ float sc[];
    const int b0 = blockIdx.x * 16;
    const int tid = threadIdx.x;
    const float4* g = (const float4*)(caps + (size_t)b0 * 1600);
    float4* s4 = (float4*)sc;
    for (int i = tid; i < 6400; i += 256) s4[i] = g[i];
    __syncthreads();

    for (int t = tid; t < 400; t += 256) {
        int bs = t / 25;
        int c4 = (t % 25) * 4;
        const float* crow = &sc[bs * 1600];
        float4 acc = *(const float4*)&bc[c4];
#pragma unroll 4
        for (int k = 0; k < 1600; ++k) {
            float cv = crow[k];
            float4 w = *(const float4*)&Wc[k * NLAB + c4];
            acc.x = fmaf(cv, w.x, acc.x);
            acc.y = fmaf(cv, w.y, acc.y);
            acc.z = fmaf(cv, w.z, acc.z);
            acc.w = fmaf(cv, w.w, acc.w);
        }
        *(float4*)&out[(size_t)(b0 + bs) * NLAB + c4] = acc;
    }
}

// ---------------- launch -----------------------------------------------------
extern "C" void kernel_launch(void* const* d_in, const int* in_sizes, int n_in,
                              void* d_out, int out_size)
{
    const float* F  = (const float*)d_in[0];
    const float* W1 = (const float*)d_in[1];
    const float* b1 = (const float*)d_in[2];
    const float* W2 = (const float*)d_in[3];
    const float* b2 = (const float*)d_in[4];
    const float* Wp = (const float*)d_in[5];
    const float* bp = (const float*)d_in[6];
    const float* lg = (const float*)d_in[7];
    const float* lb = (const float*)d_in[8];
    const float* Wr = (const float*)d_in[9];
    const float* Wc = (const float*)d_in[10];
    const float* bc = (const float*)d_in[11];
    float* out = (float*)d_out;
    (void)in_sizes; (void)n_in; (void)out_size;

    __nv_bfloat16 *fhi, *flo, *whi, *wlo;
    float *h1, *h2, *p, *wpt, *pr, *caps;
    cudaGetSymbolAddress((void**)&fhi,  g_Fhi);
    cudaGetSymbolAddress((void**)&flo,  g_Flo);
    cudaGetSymbolAddress((void**)&whi,  g_W1Thi);
    cudaGetSymbolAddress((void**)&wlo,  g_W1Tlo);
    cudaGetSymbolAddress((void**)&h1,   g_h1);
    cudaGetSymbolAddress((void**)&h2,   g_h2);
    cudaGetSymbolAddress((void**)&p,    g_p);
    cudaGetSymbolAddress((void**)&wpt,  g_WpT);
    cudaGetSymbolAddress((void**)&pr,   g_preds);
    cudaGetSymbolAddress((void**)&caps, g_caps);

    cudaFuncSetAttribute((const void*)gemm1_bf16,
                         cudaFuncAttributeMaxDynamicSharedMemorySize, 2 * STG_BYTES);
    cudaFuncSetAttribute((const void*)preds_kernel,
                         cudaFuncAttributeMaxDynamicSharedMemorySize, 55296);
    cudaFuncSetAttribute((const void*)routing_kernel,
                         cudaFuncAttributeMaxDynamicSharedMemorySize, 224512);
    cudaFuncSetAttribute((const void*)final_gemm,
                         cudaFuncAttributeMaxDynamicSharedMemorySize, 102400);

    pack_wp<<<256, 256>>>(Wp, wpt);
    convert_F<<<dim3(40, BATCH), 256>>>(F, fhi, flo);
    convert_W1T<<<dim3(KPAD / 32, H1DIM / 32), dim3(32, 8)>>>(W1, whi, wlo);
    gemm1_bf16<<<dim3(4, 32), 256, 2 * STG_BYTES>>>(fhi, flo, whi, wlo, b1, h1);
    sgemm_k<true ><<<dim3(2, 32), 256>>>(h1, W2,  b2, h2, BATCH, H2DIM, H1DIM);
    sgemm_k<false><<<dim3(2, 32), 256>>>(h2, wpt, bp, p,  BATCH, H2DIM, H2DIM);
    ln_kernel<<<(BATCH * NPRIM) / 256, 256>>>(p, lg, lb);
    preds_kernel<<<dim3(BATCH / 128, NPRIM), 256, 55296>>>(p, Wr, pr);
    routing_kernel<<<BATCH, 256, 224512>>>(pr, caps);
    final_gemm<<<BATCH / 16, 256, 102400>>>(caps, Wc, bc, out);
}

// round 6
// speedup vs baseline: 1.5552x; 1.2815x over previous
#include <cuda_runtime.h>
#include <cuda_bf16.h>
#include <cstdint>
#include <cstddef>

// Problem constants
#define BATCH   4096
#define INDIM   10000
#define KPAD    10240      // padded K, = 4 * 2560
#define KSEG    2560       // K per split (gemm1)
#define NSPLIT  4
#define H1DIM   512
#define H2DIM   256
#define NPRIM   32
#define PDIM    8
#define NLAB    100
#define NLABP   128        // padded label dim for final gemm
#define CDIM    16
#define FK      1600       // final gemm K = 100*16
#define FKSEG   400
#define PREDROW 51200      // 32*100*16

// ---------------- scratch (static device arrays; cudaMalloc forbidden) ------
__device__ __nv_bfloat16 g_Fhi[(size_t)BATCH * KPAD];
__device__ __nv_bfloat16 g_Flo[(size_t)BATCH * KPAD];
__device__ __nv_bfloat16 g_W1Thi[(size_t)H1DIM * KPAD];
__device__ __nv_bfloat16 g_W1Tlo[(size_t)H1DIM * KPAD];
__device__ float g_part1[NSPLIT][(size_t)BATCH * H1DIM];   // gemm1 partials
__device__ float g_h1[(size_t)BATCH * H1DIM];
__device__ float g_h2[(size_t)BATCH * H2DIM];
__device__ float g_p [(size_t)BATCH * H2DIM];
__device__ float g_WpT[H2DIM * (NPRIM * PDIM)];
__device__ float g_preds[(size_t)BATCH * PREDROW];         // 839 MB
__device__ float g_caps[(size_t)BATCH * NLAB * CDIM];
__device__ float g_WcP[(size_t)FK * NLABP];                // padded Wc
__device__ float g_fpart[NSPLIT][(size_t)BATCH * NLABP];   // final partials

// ---------------- conversions ------------------------------------------------
__global__ void convert_F(const float* __restrict__ F,
                          __nv_bfloat16* __restrict__ hi,
                          __nv_bfloat16* __restrict__ lo)
{
    int k = blockIdx.x * 256 + threadIdx.x;
    int b = blockIdx.y;
    if (k >= KPAD) return;
    float x = (k < INDIM) ? F[(size_t)b * INDIM + k] : 0.f;
    __nv_bfloat16 h = __float2bfloat16_rn(x);
    float r = x - __bfloat162float(h);
    hi[(size_t)b * KPAD + k] = h;
    lo[(size_t)b * KPAD + k] = __float2bfloat16_rn(r);
}

__global__ void convert_W1T(const float* __restrict__ W1,
                            __nv_bfloat16* __restrict__ hi,
                            __nv_bfloat16* __restrict__ lo)
{
    __shared__ float tile[32][33];
    int k0 = blockIdx.x * 32;
    int n0 = blockIdx.y * 32;
    int tx = threadIdx.x, ty = threadIdx.y;   // 32 x 8
#pragma unroll
    for (int i = 0; i < 4; ++i) {
        int k = k0 + ty + i * 8;
        tile[ty + i * 8][tx] = (k < INDIM) ? W1[(size_t)k * H1DIM + n0 + tx] : 0.f;
    }
    __syncthreads();
#pragma unroll
    for (int i = 0; i < 4; ++i) {
        int n = n0 + ty + i * 8;
        int k = k0 + tx;
        float x = tile[tx][ty + i * 8];
        __nv_bfloat16 h = __float2bfloat16_rn(x);
        float r = x - __bfloat162float(h);
        hi[(size_t)n * KPAD + k] = h;
        lo[(size_t)n * KPAD + k] = __float2bfloat16_rn(r);
    }
}

// ---------------- cp.async + mma helpers -------------------------------------
__device__ __forceinline__ void cp16(uint32_t dst, const void* src) {
    asm volatile("cp.async.cg.shared.global [%0], [%1], 16;\n" :: "r"(dst), "l"(src));
}
__device__ __forceinline__ void cp_commit() {
    asm volatile("cp.async.commit_group;\n");
}
template <int N>
__device__ __forceinline__ void cp_wait() {
    asm volatile("cp.async.wait_group %0;\n" :: "n"(N));
}
__device__ __forceinline__ void mma_bf16(float* d,
    uint32_t a0, uint32_t a1, uint32_t a2, uint32_t a3,
    uint32_t b0, uint32_t b1)
{
    asm volatile(
        "mma.sync.aligned.m16n8k16.row.col.f32.bf16.bf16.f32 "
        "{%0,%1,%2,%3}, {%4,%5,%6,%7}, {%8,%9}, {%0,%1,%2,%3};\n"
        : "+f"(d[0]), "+f"(d[1]), "+f"(d[2]), "+f"(d[3])
        : "r"(a0), "r"(a1), "r"(a2), "r"(a3), "r"(b0), "r"(b1));
}

// ---------------- GEMM1: bf16 split 3-term MMA, split-K=4 --------------------
// BM=128, BN=128, BK=32, 256 threads, warp tile 64x32. Partial fp32 out.
#define STG_BYTES 40960
#define ROWU32 20

__global__ void __launch_bounds__(256, 2) gemm1_bf16(
    const __nv_bfloat16* __restrict__ Ahi, const __nv_bfloat16* __restrict__ Alo,
    const __nv_bfloat16* __restrict__ Bhi, const __nv_bfloat16* __restrict__ Blo,
    float* __restrict__ Cpart)
{
    extern __shared__ __align__(16) char dsm[];
    const int tid  = threadIdx.x;
    const int lane = tid & 31, warp = tid >> 5;
    const int g = lane >> 2, tg = lane & 3;
    const int wm = warp >> 2, wn = warp & 3;
    const int m0 = blockIdx.y * 128;
    const int n0 = blockIdx.x * 128;
    const int kbase = blockIdx.z * KSEG;

    uint32_t smem_u32;
    { void* pp = dsm; smem_u32 = (uint32_t)__cvta_generic_to_shared(pp); }

    const int c0 = tid, c1 = tid + 256;
    const int r0 = c0 >> 2, kc0 = c0 & 3;
    const int r1 = c1 >> 2, kc1 = c1 & 3;

    float acc[4][4][4];
#pragma unroll
    for (int a = 0; a < 4; ++a)
#pragma unroll
        for (int b = 0; b < 4; ++b)
#pragma unroll
            for (int d = 0; d < 4; ++d) acc[a][b][d] = 0.f;

    const int NSTEP = KSEG / 32;   // 80

    auto load_stage = [&](int stage, int k0) {
        uint32_t base = smem_u32 + stage * STG_BYTES;
        cp16(base + r0 * 80 + kc0 * 16,          Ahi + (size_t)(m0 + r0) * KPAD + k0 + kc0 * 8);
        cp16(base + r1 * 80 + kc1 * 16,          Ahi + (size_t)(m0 + r1) * KPAD + k0 + kc1 * 8);
        cp16(base + 10240 + r0 * 80 + kc0 * 16,  Alo + (size_t)(m0 + r0) * KPAD + k0 + kc0 * 8);
        cp16(base + 10240 + r1 * 80 + kc1 * 16,  Alo + (size_t)(m0 + r1) * KPAD + k0 + kc1 * 8);
        cp16(base + 20480 + r0 * 80 + kc0 * 16,  Bhi + (size_t)(n0 + r0) * KPAD + k0 + kc0 * 8);
        cp16(base + 20480 + r1 * 80 + kc1 * 16,  Bhi + (size_t)(n0 + r1) * KPAD + k0 + kc1 * 8);
        cp16(base + 30720 + r0 * 80 + kc0 * 16,  Blo + (size_t)(n0 + r0) * KPAD + k0 + kc0 * 8);
        cp16(base + 30720 + r1 * 80 + kc1 * 16,  Blo + (size_t)(n0 + r1) * KPAD + k0 + kc1 * 8);
    };

    load_stage(0, kbase);
    cp_commit();

    for (int it = 0; it < NSTEP; ++it) {
        const int stage = it & 1;
        if (it + 1 < NSTEP) {
            load_stage(stage ^ 1, kbase + (it + 1) * 32);
            cp_commit();
            cp_wait<1>();
        } else {
            cp_wait<0>();
        }
        __syncthreads();

        const uint32_t* Ah = (const uint32_t*)(dsm + stage * STG_BYTES);
        const uint32_t* Al = Ah + 10240 / 4;
        const uint32_t* Bh = Ah + 20480 / 4;
        const uint32_t* Bl = Ah + 30720 / 4;

#pragma unroll
        for (int ks = 0; ks < 2; ++ks) {
            uint32_t ah[4][4], al[4][4], bh[4][2], bl[4][2];
#pragma unroll
            for (int mi = 0; mi < 4; ++mi) {
                int row = wm * 64 + mi * 16 + g;
                int o = ks * 8 + tg;
                ah[mi][0] = Ah[row * ROWU32 + o];
                ah[mi][1] = Ah[(row + 8) * ROWU32 + o];
                ah[mi][2] = Ah[row * ROWU32 + o + 4];
                ah[mi][3] = Ah[(row + 8) * ROWU32 + o + 4];
                al[mi][0] = Al[row * ROWU32 + o];
                al[mi][1] = Al[(row + 8) * ROWU32 + o];
                al[mi][2] = Al[row * ROWU32 + o + 4];
                al[mi][3] = Al[(row + 8) * ROWU32 + o + 4];
            }
#pragma unroll
            for (int ni = 0; ni < 4; ++ni) {
                int row = wn * 32 + ni * 8 + g;
                int o = ks * 8 + tg;
                bh[ni][0] = Bh[row * ROWU32 + o];
                bh[ni][1] = Bh[row * ROWU32 + o + 4];
                bl[ni][0] = Bl[row * ROWU32 + o];
                bl[ni][1] = Bl[row * ROWU32 + o + 4];
            }
#pragma unroll
            for (int mi = 0; mi < 4; ++mi)
#pragma unroll
                for (int ni = 0; ni < 4; ++ni) {
                    mma_bf16(acc[mi][ni], ah[mi][0], ah[mi][1], ah[mi][2], ah[mi][3],
                             bh[ni][0], bh[ni][1]);
                    mma_bf16(acc[mi][ni], ah[mi][0], ah[mi][1], ah[mi][2], ah[mi][3],
                             bl[ni][0], bl[ni][1]);
                    mma_bf16(acc[mi][ni], al[mi][0], al[mi][1], al[mi][2], al[mi][3],
                             bh[ni][0], bh[ni][1]);
                }
        }
        __syncthreads();
    }

    float* P = Cpart + (size_t)blockIdx.z * BATCH * H1DIM;
#pragma unroll
    for (int mi = 0; mi < 4; ++mi) {
        int row = m0 + wm * 64 + mi * 16 + g;
#pragma unroll
        for (int ni = 0; ni < 4; ++ni) {
            int col = n0 + wn * 32 + ni * 8 + tg * 2;
            *(float2*)&P[(size_t)row * H1DIM + col] =
                make_float2(acc[mi][ni][0], acc[mi][ni][1]);
            *(float2*)&P[(size_t)(row + 8) * H1DIM + col] =
                make_float2(acc[mi][ni][2], acc[mi][ni][3]);
        }
    }
}

// ---------------- combine 4 partials + bias + relu ---------------------------
__global__ void combine4_relu(const float* __restrict__ part,
                              const float* __restrict__ bias,
                              float* __restrict__ out)
{
    int idx = blockIdx.x * 256 + threadIdx.x;    // float4 index
    const size_t STRIDE = (size_t)BATCH * H1DIM;
    float4 a = ((const float4*)part)[idx];
    float4 b = ((const float4*)(part + STRIDE))[idx];
    float4 c = ((const float4*)(part + 2 * STRIDE))[idx];
    float4 d = ((const float4*)(part + 3 * STRIDE))[idx];
    int col4 = (idx & (H1DIM / 4 - 1)) << 2;
    float4 bi = *(const float4*)&bias[col4];
    float4 r;
    r.x = fmaxf(a.x + b.x + c.x + d.x + bi.x, 0.f);
    r.y = fmaxf(a.y + b.y + c.y + d.y + bi.y, 0.f);
    r.z = fmaxf(a.z + b.z + c.z + d.z + bi.z, 0.f);
    r.w = fmaxf(a.w + b.w + c.w + d.w + bi.w, 0.f);
    ((float4*)out)[idx] = r;
}

// ---------------- K0: pack Wp [n][i][o] -> WpT [i][n*8+o] --------------------
__global__ void pack_wp(const float* __restrict__ Wp, float* __restrict__ WpT) {
    int idx = blockIdx.x * 256 + threadIdx.x;
    int i = idx >> 8;
    int c = idx & 255;
    int n = c >> 3, o = c & 7;
    WpT[idx] = Wp[((size_t)(n << 8) + i) * 8 + o];
}

// ---------------- pack Wc 1600x100 -> 1600x128 (zero pad) --------------------
__global__ void pack_wc(const float* __restrict__ Wc, float* __restrict__ WcP) {
    int idx = blockIdx.x * 256 + threadIdx.x;   // 1600*128
    int k = idx >> 7, c = idx & 127;
    WcP[idx] = (c < NLAB) ? Wc[k * NLAB + c] : 0.f;
}

// ---------------- fp32 SIMT SGEMM core ---------------------------------------
struct TileCtx { int arow, acol, brow, bcol, ry, cx; };
__device__ __forceinline__ void tile_init(TileCtx& t, int tid) {
    t.arow = tid >> 1;  t.acol = (tid & 1) << 2;
    t.brow = tid >> 5;  t.bcol = (tid & 31) << 2;
    t.ry = (tid >> 4) << 3;  t.cx = (tid & 15) << 3;
}
__device__ __forceinline__ void tile_mainloop(
    const TileCtx& t, const float* Ap, const float* Bp, int N, int K,
    float (*As)[8][128], float (*Bs)[8][128], float acc[8][8])
{
    {
        float4 av = *(const float4*)(Ap);
        float4 bv = *(const float4*)(Bp);
        As[0][t.acol + 0][t.arow] = av.x;
        As[0][t.acol + 1][t.arow] = av.y;
        As[0][t.acol + 2][t.arow] = av.z;
        As[0][t.acol + 3][t.arow] = av.w;
        *(float4*)&Bs[0][t.brow][t.bcol] = bv;
    }
    __syncthreads();
    for (int k0 = 0; k0 < K; k0 += 8) {
        const int cur = (k0 >> 3) & 1;
        float4 av, bv;
        const bool more = (k0 + 8) < K;
        if (more) {
            av = *(const float4*)(Ap + k0 + 8);
            bv = *(const float4*)(Bp + (size_t)(k0 + 8) * N);
        }
#pragma unroll
        for (int kk = 0; kk < 8; ++kk) {
            float a[8], b[8];
            *(float4*)&a[0] = *(float4*)&As[cur][kk][t.ry];
            *(float4*)&a[4] = *(float4*)&As[cur][kk][t.ry + 4];
            *(float4*)&b[0] = *(float4*)&Bs[cur][kk][t.cx];
            *(float4*)&b[4] = *(float4*)&Bs[cur][kk][t.cx + 4];
#pragma unroll
            for (int i = 0; i < 8; ++i)
#pragma unroll
                for (int j = 0; j < 8; ++j) acc[i][j] += a[i] * b[j];
        }
        if (more) {
            const int nxt = cur ^ 1;
            As[nxt][t.acol + 0][t.arow] = av.x;
            As[nxt][t.acol + 1][t.arow] = av.y;
            As[nxt][t.acol + 2][t.arow] = av.z;
            As[nxt][t.acol + 3][t.arow] = av.w;
            *(float4*)&Bs[nxt][t.brow][t.bcol] = bv;
        }
        __syncthreads();
    }
}

template <bool RELU>
__global__ void __launch_bounds__(256) sgemm_k(
    const float* __restrict__ A, const float* __restrict__ Bm,
    const float* __restrict__ bias, float* __restrict__ C,
    int M, int N, int K)
{
    __shared__ float As[2][8][128];
    __shared__ float Bs[2][8][128];
    TileCtx t; tile_init(t, threadIdx.x);
    const int m0 = blockIdx.y * 128;
    const int n0 = blockIdx.x * 128;

    float acc[8][8];
#pragma unroll
    for (int i = 0; i < 8; ++i)
#pragma unroll
        for (int j = 0; j < 8; ++j) acc[i][j] = 0.f;

    tile_mainloop(t, A + (size_t)(m0 + t.arow) * K + t.acol,
                  Bm + (size_t)t.brow * N + n0 + t.bcol, N, K, As, Bs, acc);

    float4 bia = *(const float4*)&bias[n0 + t.cx];
    float4 bib = *(const float4*)&bias[n0 + t.cx + 4];
#pragma unroll
    for (int i = 0; i < 8; ++i) {
        float4 v0, v1;
        v0.x = acc[i][0] + bia.x; v0.y = acc[i][1] + bia.y;
        v0.z = acc[i][2] + bia.z; v0.w = acc[i][3] + bia.w;
        v1.x = acc[i][4] + bib.x; v1.y = acc[i][5] + bib.y;
        v1.z = acc[i][6] + bib.z; v1.w = acc[i][7] + bib.w;
        if (RELU) {
            v0.x = fmaxf(v0.x, 0.f); v0.y = fmaxf(v0.y, 0.f);
            v0.z = fmaxf(v0.z, 0.f); v0.w = fmaxf(v0.w, 0.f);
            v1.x = fmaxf(v1.x, 0.f); v1.y = fmaxf(v1.y, 0.f);
            v1.z = fmaxf(v1.z, 0.f); v1.w = fmaxf(v1.w, 0.f);
        }
        float* cp = C + (size_t)(m0 + t.ry + i) * N + n0 + t.cx;
        *(float4*)cp = v0;
        *(float4*)(cp + 4) = v1;
    }
}

// split-K fp32 sgemm for the final projection (partial, no bias)
__global__ void __launch_bounds__(256) sgemm_splitk_f(
    const float* __restrict__ A, const float* __restrict__ Bm,
    float* __restrict__ Cpart, int M, int N, int K, int kseg)
{
    __shared__ float As[2][8][128];
    __shared__ float Bs[2][8][128];
    TileCtx t; tile_init(t, threadIdx.x);
    const int m0 = blockIdx.y * 128;
    const int n0 = blockIdx.x * 128;
    const int z  = blockIdx.z;
    const int kOff = z * kseg;

    float acc[8][8];
#pragma unroll
    for (int i = 0; i < 8; ++i)
#pragma unroll
        for (int j = 0; j < 8; ++j) acc[i][j] = 0.f;

    tile_mainloop(t, A + (size_t)(m0 + t.arow) * K + kOff + t.acol,
                  Bm + (size_t)(kOff + t.brow) * N + n0 + t.bcol,
                  N, kseg, As, Bs, acc);

    float* Cz = Cpart + (size_t)z * M * N;
#pragma unroll
    for (int i = 0; i < 8; ++i) {
        float* cp = Cz + (size_t)(m0 + t.ry + i) * N + n0 + t.cx;
        *(float4*)cp       = *(float4*)&acc[i][0];
        *(float4*)(cp + 4) = *(float4*)&acc[i][4];
    }
}

// combine final partials + bias, write guarded 100-col output
__global__ void combine_final(const float* __restrict__ part,
                              const float* __restrict__ bc,
                              float* __restrict__ out)
{
    int idx = blockIdx.x * 256 + threadIdx.x;   // over 4096*25 float4s
    if (idx >= BATCH * 25) return;
    int b = idx / 25;
    int c4 = (idx % 25) * 4;
    const size_t STRIDE = (size_t)BATCH * NLABP;
    const float* base = part + (size_t)b * NLABP + c4;
    float4 a = *(const float4*)base;
    float4 e = *(const float4*)(base + STRIDE);
    float4 c = *(const float4*)(base + 2 * STRIDE);
    float4 d = *(const float4*)(base + 3 * STRIDE);
    float4 bi = *(const float4*)&bc[c4];
    float4 r;
    r.x = a.x + e.x + c.x + d.x + bi.x;
    r.y = a.y + e.y + c.y + d.y + bi.y;
    r.z = a.z + e.z + c.z + d.z + bi.z;
    r.w = a.w + e.w + c.w + d.w + bi.w;
    *(float4*)&out[(size_t)b * NLAB + c4] = r;
}

// ---------------- LayerNorm over last dim (8) per (b, n) ---------------------
__global__ void ln_kernel(float* __restrict__ p,
                          const float* __restrict__ g,
                          const float* __restrict__ be)
{
    int idx = blockIdx.x * 256 + threadIdx.x;
    int n = idx & (NPRIM - 1);
    float* row = p + (size_t)idx * 8;
    float4 a = *(float4*)row;
    float4 b = *(float4*)(row + 4);
    float x[8] = {a.x, a.y, a.z, a.w, b.x, b.y, b.z, b.w};
    float mu = 0.f;
#pragma unroll
    for (int i = 0; i < 8; ++i) mu += x[i];
    mu *= 0.125f;
    float var = 0.f;
#pragma unroll
    for (int i = 0; i < 8; ++i) { float d = x[i] - mu; var += d * d; }
    var *= 0.125f;
    float inv = rsqrtf(var + 1e-5f);
    const float* gr = g + n * 8;
    const float* br = be + n * 8;
#pragma unroll
    for (int i = 0; i < 8; ++i) x[i] = (x[i] - mu) * inv * gr[i] + br[i];
    a.x = x[0]; a.y = x[1]; a.z = x[2]; a.w = x[3];
    b.x = x[4]; b.y = x[5]; b.z = x[6]; b.w = x[7];
    *(float4*)row = a;
    *(float4*)(row + 4) = b;
}

// ---------------- preds[b][n][j][o] = sum_i p[b][n][i] * Wr[n][j][o][i] ------
__global__ void __launch_bounds__(256) preds_kernel(
    const float* __restrict__ p, const float* __restrict__ Wr,
    float* __restrict__ preds)
{
    extern __shared__ float sm4[];
    float* ws = sm4;
    float* ps = sm4 + 12800;
    const int n  = blockIdx.y;
    const int b0 = blockIdx.x * 128;
    const int tid = threadIdx.x;
    const int lane = tid & 31, warp = tid >> 5;

    const float4* wg = (const float4*)(Wr + (size_t)n * 12800);
    float4* ws4 = (float4*)ws;
    for (int i = tid; i < 3200; i += 256) ws4[i] = wg[i];
    {
        int bb = tid >> 1, h = tid & 1;
        *(float4*)&ps[bb * 8 + h * 4] =
            *(const float4*)(p + (size_t)(b0 + bb) * 256 + n * 8 + h * 4);
    }
    __syncthreads();

    for (int chunk = warp; chunk < 13; chunk += 8) {
        int row0 = chunk * 128 + lane * 4;
        if (row0 >= 1600) continue;
        float w[4][8];
#pragma unroll
        for (int r = 0; r < 4; ++r) {
            float4 wa = *(float4*)&ws[(row0 + r) * 8];
            float4 wb = *(float4*)&ws[(row0 + r) * 8 + 4];
            w[r][0] = wa.x; w[r][1] = wa.y; w[r][2] = wa.z; w[r][3] = wa.w;
            w[r][4] = wb.x; w[r][5] = wb.y; w[r][6] = wb.z; w[r][7] = wb.w;
        }
#pragma unroll 2
        for (int bb = 0; bb < 128; ++bb) {
            float4 pa = *(float4*)&ps[bb * 8];
            float4 pb = *(float4*)&ps[bb * 8 + 4];
            float pv[8] = {pa.x, pa.y, pa.z, pa.w, pb.x, pb.y, pb.z, pb.w};
            float4 o;
            float* acc = (float*)&o;
#pragma unroll
            for (int r = 0; r < 4; ++r) {
                float s = 0.f;
#pragma unroll
                for (int i = 0; i < 8; ++i) s = fmaf(w[r][i], pv[i], s);
                acc[r] = s;
            }
            *(float4*)&preds[((size_t)(b0 + bb) * NPRIM + n) * 1600 + row0] = o;
        }
    }
}

// ---------------- dynamic routing, one CTA per batch element -----------------
// Fused: the global->smem preds copy also accumulates s0 = 0.01 * sum_n preds.
__global__ void __launch_bounds__(256) routing_kernel(
    const float* __restrict__ preds, float* __restrict__ caps)
{
    extern __shared__ float sm[];
    float* sp = sm;                 // 51200
    float* Cw = sp + 51200;         // 3200
    float* S  = Cw + 3200;          // 1600
    float* SQ = S + 1600;           // 128
    const int tid = threadIdx.x;
    const int lane = tid & 31, warp = tid >> 5;
    const size_t b = blockIdx.x;

    const float4* g = (const float4*)(preds + b * PREDROW);
    float4* sp4 = (float4*)sp;
    float4* S4 = (float4*)S;

    // fused load + iteration-0 s accumulation
    float4 a0 = {0.f, 0.f, 0.f, 0.f};
    float4 a1 = {0.f, 0.f, 0.f, 0.f};
    const bool has2 = (tid + 256) < 400;
#pragma unroll 4
    for (int n = 0; n < NPRIM; ++n) {
        const float4* row = g + n * 400;
        float4 v0 = row[tid];
        sp4[n * 400 + tid] = v0;
        a0.x += v0.x; a0.y += v0.y; a0.z += v0.z; a0.w += v0.w;
        if (has2) {
            float4 v1 = row[tid + 256];
            sp4[n * 400 + tid + 256] = v1;
            a1.x += v1.x; a1.y += v1.y; a1.z += v1.z; a1.w += v1.w;
        }
    }
    S4[tid] = make_float4(0.01f * a0.x, 0.01f * a0.y, 0.01f * a0.z, 0.01f * a0.w);
    if (has2)
        S4[tid + 256] = make_float4(0.01f * a1.x, 0.01f * a1.y, 0.01f * a1.z, 0.01f * a1.w);
    __syncthreads();

    float bl[4][4];
#pragma unroll
    for (int q = 0; q < 4; ++q)
#pragma unroll
        for (int t = 0; t < 4; ++t) bl[q][t] = 0.f;

    for (int it = 0; it < 3; ++it) {
        if (it > 0) {
            // softmax from bl -> Cw
#pragma unroll
            for (int q = 0; q < 4; ++q) {
                int n = warp * 4 + q;
                float m = -1e30f;
#pragma unroll
                for (int t = 0; t < 4; ++t) {
                    int j = lane + 32 * t;
                    if (j < NLAB) m = fmaxf(m, bl[q][t]);
                }
#pragma unroll
                for (int off = 16; off; off >>= 1)
                    m = fmaxf(m, __shfl_xor_sync(0xffffffffu, m, off));
                float e[4]; float s = 0.f;
#pragma unroll
                for (int t = 0; t < 4; ++t) {
                    int j = lane + 32 * t;
                    e[t] = (j < NLAB) ? __expf(bl[q][t] - m) : 0.f;
                    s += e[t];
                }
#pragma unroll
                for (int off = 16; off; off >>= 1)
                    s += __shfl_xor_sync(0xffffffffu, s, off);
                float inv = 1.f / s;
#pragma unroll
                for (int t = 0; t < 4; ++t) {
                    int j = lane + 32 * t;
                    if (j < NLAB) Cw[n * NLAB + j] = e[t] * inv;
                }
            }
            __syncthreads();

            // s = sum_n c * preds
            for (int idx = tid; idx < 400; idx += 256) {
                int j = idx >> 2, o4 = (idx & 3) << 2;
                float4 acc = {0.f, 0.f, 0.f, 0.f};
#pragma unroll 4
                for (int n = 0; n < NPRIM; ++n) {
                    float c = Cw[n * NLAB + j];
                    float4 pv = *(float4*)&sp[((n * NLAB + j) << 4) + o4];
                    acc.x = fmaf(c, pv.x, acc.x);
                    acc.y = fmaf(c, pv.y, acc.y);
                    acc.z = fmaf(c, pv.z, acc.z);
                    acc.w = fmaf(c, pv.w, acc.w);
                }
                *(float4*)&S[(j << 4) + o4] = acc;
            }
            __syncthreads();
        }

        // squash
        for (int j = tid; j < NLAB; j += 256) {
            float sq = 0.f;
#pragma unroll
            for (int o = 0; o < CDIM; ++o) { float v = S[(j << 4) + o]; sq = fmaf(v, v, sq); }
            SQ[j] = sq;
        }
        __syncthreads();
        for (int idx = tid; idx < 400; idx += 256) {
            int j = idx >> 2, o4 = (idx & 3) << 2;
            float sq = SQ[j];
            float scale = sq / ((1.f + sq) * sqrtf(sq + 1e-8f));
            float4 v = *(float4*)&S[(j << 4) + o4];
            v.x *= scale; v.y *= scale; v.z *= scale; v.w *= scale;
            *(float4*)&S[(j << 4) + o4] = v;
        }
        __syncthreads();

        if (it < 2) {
            // agreement: bl += <preds, v>
#pragma unroll
            for (int q = 0; q < 4; ++q) {
                int n = warp * 4 + q;
#pragma unroll
                for (int t = 0; t < 4; ++t) {
                    int j = lane + 32 * t;
                    if (j < NLAB) {
                        const float* pr = &sp[(n * NLAB + j) << 4];
                        const float* vv = &S[j << 4];
                        float a = 0.f;
#pragma unroll
                        for (int o = 0; o < CDIM; o += 4) {
                            float4 pv = *(float4*)&pr[o];
                            float4 sv = *(float4*)&vv[o];
                            a = fmaf(pv.x, sv.x, a);
                            a = fmaf(pv.y, sv.y, a);
                            a = fmaf(pv.z, sv.z, a);
                            a = fmaf(pv.w, sv.w, a);
                        }
                        bl[q][t] += a;
                    }
                }
            }
            __syncthreads();
        } else {
            for (int idx = tid; idx < 400; idx += 256) {
                int j = idx >> 2, o4 = (idx & 3) << 2;
                *(float4*)&caps[b * 1600 + (j << 4) + o4] = *(float4*)&S[(j << 4) + o4];
            }
        }
    }
}

// ---------------- launch -----------------------------------------------------
extern "C" void kernel_launch(void* const* d_in, const int* in_sizes, int n_in,
                              void* d_out, int out_size)
{
    const float* F  = (const float*)d_in[0];
    const float* W1 = (const float*)d_in[1];
    const float* b1 = (const float*)d_in[2];
    const float* W2 = (const float*)d_in[3];
    const float* b2 = (const float*)d_in[4];
    const float* Wp = (const float*)d_in[5];
    const float* bp = (const float*)d_in[6];
    const float* lg = (const float*)d_in[7];
    const float* lb = (const float*)d_in[8];
    const float* Wr = (const float*)d_in[9];
    const float* Wc = (const float*)d_in[10];
    const float* bc = (const float*)d_in[11];
    float* out = (float*)d_out;
    (void)in_sizes; (void)n_in; (void)out_size;

    __nv_bfloat16 *fhi, *flo, *whi, *wlo;
    float *part1, *h1, *h2, *p, *wpt, *pr, *caps, *wcp, *fpart;
    cudaGetSymbolAddress((void**)&fhi,   g_Fhi);
    cudaGetSymbolAddress((void**)&flo,   g_Flo);
    cudaGetSymbolAddress((void**)&whi,   g_W1Thi);
    cudaGetSymbolAddress((void**)&wlo,   g_W1Tlo);
    cudaGetSymbolAddress((void**)&part1, g_part1);
    cudaGetSymbolAddress((void**)&h1,    g_h1);
    cudaGetSymbolAddress((void**)&h2,    g_h2);
    cudaGetSymbolAddress((void**)&p,     g_p);
    cudaGetSymbolAddress((void**)&wpt,   g_WpT);
    cudaGetSymbolAddress((void**)&pr,    g_preds);
    cudaGetSymbolAddress((void**)&caps,  g_caps);
    cudaGetSymbolAddress((void**)&wcp,   g_WcP);
    cudaGetSymbolAddress((void**)&fpart, g_fpart);

    cudaFuncSetAttribute((const void*)gemm1_bf16,
                         cudaFuncAttributeMaxDynamicSharedMemorySize, 2 * STG_BYTES);
    cudaFuncSetAttribute((const void*)preds_kernel,
                         cudaFuncAttributeMaxDynamicSharedMemorySize, 55296);
    cudaFuncSetAttribute((const void*)routing_kernel,
                         cudaFuncAttributeMaxDynamicSharedMemorySize, 224512);

    pack_wp<<<256, 256>>>(Wp, wpt);
    pack_wc<<<800, 256>>>(Wc, wcp);
    convert_F<<<dim3(KPAD / 256, BATCH), 256>>>(F, fhi, flo);
    convert_W1T<<<dim3(KPAD / 32, H1DIM / 32), dim3(32, 8)>>>(W1, whi, wlo);
    gemm1_bf16<<<dim3(4, 32, NSPLIT), 256, 2 * STG_BYTES>>>(fhi, flo, whi, wlo, part1);
    combine4_relu<<<(BATCH * H1DIM) / 4 / 256, 256>>>(part1, b1, h1);
    sgemm_k<true ><<<dim3(2, 32), 256>>>(h1, W2,  b2, h2, BATCH, H2DIM, H1DIM);
    sgemm_k<false><<<dim3(2, 32), 256>>>(h2, wpt, bp, p,  BATCH, H2DIM, H2DIM);
    ln_kernel<<<(BATCH * NPRIM) / 256, 256>>>(p, lg, lb);
    preds_kernel<<<dim3(BATCH / 128, NPRIM), 256, 55296>>>(p, Wr, pr);
    routing_kernel<<<BATCH, 256, 224512>>>(pr, caps);
    sgemm_splitk_f<<<dim3(1, 32, NSPLIT), 256>>>(caps, wcp, fpart,
                                                 BATCH, NLABP, FK, FKSEG);
    combine_final<<<(BATCH * 25 + 255) / 256, 256>>>(fpart, bc, out);
}